// round 3
// baseline (speedup 1.0000x reference)
#include <cuda_runtime.h>
#include <cuda_bf16.h>

// SuctionNet: out[0..n)   = w0 . feats[idx[p]] + b0   (seal)
//             out[n..2n)  = w1 . feats[idx[p]] + b1   (wrench)
// feats: [150000, 256] f32, idx: [200000] int32 (JAX x64-off downcasts int64),
// w: [2,256] f32, b: [2] f32
//
// HBM-gather-bound: warp per point, lane l owns channels [8l, 8l+8).
// Weights hoisted to registers, grid-stride loop amortizes them.

#define FEAT_DIM 256

__global__ __launch_bounds__(256, 8)
void suction_kernel(const float* __restrict__ feats,
                    const int* __restrict__ idx,
                    const float* __restrict__ w,
                    const float* __restrict__ b,
                    float* __restrict__ out,
                    int n)
{
    const int lane = threadIdx.x & 31;
    const int warp_global = (blockIdx.x * blockDim.x + threadIdx.x) >> 5;
    const int total_warps = (gridDim.x * blockDim.x) >> 5;

    // Per-lane weight slice: 8 channels for each of the 2 scoring rows.
    const float4* w0p = reinterpret_cast<const float4*>(w) + lane * 2;
    const float4* w1p = reinterpret_cast<const float4*>(w + FEAT_DIM) + lane * 2;
    const float4 w0a = __ldg(w0p);
    const float4 w0b = __ldg(w0p + 1);
    const float4 w1a = __ldg(w1p);
    const float4 w1b = __ldg(w1p + 1);
    const float b0 = __ldg(b);
    const float b1 = __ldg(b + 1);

    for (int p = warp_global; p < n; p += total_warps) {
        const long long r = (long long)__ldg(idx + p);     // broadcast across warp
        const float4* row = reinterpret_cast<const float4*>(feats + r * FEAT_DIM)
                            + lane * 2;
        const float4 fa = __ldg(row);
        const float4 fb = __ldg(row + 1);

        float s0 = fa.x * w0a.x;
        s0 = fmaf(fa.y, w0a.y, s0);
        s0 = fmaf(fa.z, w0a.z, s0);
        s0 = fmaf(fa.w, w0a.w, s0);
        s0 = fmaf(fb.x, w0b.x, s0);
        s0 = fmaf(fb.y, w0b.y, s0);
        s0 = fmaf(fb.z, w0b.z, s0);
        s0 = fmaf(fb.w, w0b.w, s0);

        float s1 = fa.x * w1a.x;
        s1 = fmaf(fa.y, w1a.y, s1);
        s1 = fmaf(fa.z, w1a.z, s1);
        s1 = fmaf(fa.w, w1a.w, s1);
        s1 = fmaf(fb.x, w1b.x, s1);
        s1 = fmaf(fb.y, w1b.y, s1);
        s1 = fmaf(fb.z, w1b.z, s1);
        s1 = fmaf(fb.w, w1b.w, s1);

        // Warp tree reduce (both accumulators).
        #pragma unroll
        for (int off = 16; off > 0; off >>= 1) {
            s0 += __shfl_xor_sync(0xFFFFFFFFu, s0, off);
            s1 += __shfl_xor_sync(0xFFFFFFFFu, s1, off);
        }

        if (lane == 0) {
            out[p]     = s0 + b0;
            out[n + p] = s1 + b1;
        }
    }
}

extern "C" void kernel_launch(void* const* d_in, const int* in_sizes, int n_in,
                              void* d_out, int out_size)
{
    const float* feats = (const float*)d_in[0];      // [150000*256]
    const int*   idx   = (const int*)d_in[1];        // [200000] int32
    const float* w     = (const float*)d_in[2];      // [2*256]
    const float* b     = (const float*)d_in[3];      // [2]
    float* out = (float*)d_out;                      // [2 * n]

    const int n = in_sizes[1];                       // 200000 points

    const int threads = 256;
    const int blocks  = 1184;                        // 148 SMs * 8 blocks
    suction_kernel<<<blocks, threads>>>(feats, idx, w, b, out, n);
}